// round 6
// baseline (speedup 1.0000x reference)
#include <cuda_runtime.h>
#include <cstdint>

// Problem constants (match reference)
#define Lc 4
#define Gc 20000
#define Cc 128
#define Ec 320000
#define KDc 16
#define NROWS (Lc*Gc)          // 80000 state rows of length 128
#define LN_EPS 1e-5f

// ---------------- device scratch (static: no allocation APIs) --------------
__device__ float g_bufA[(size_t)Lc*Gc*Cc];   // xr1
__device__ float g_bufB[(size_t)Lc*Gc*Cc];   // xr2
__device__ float g_weights[NROWS];           // flat index R = l*Gc + g
__device__ int   g_rowptr[Gc+1];
__device__ int   g_cnt[Gc];
__device__ int   g_fill[Gc];
__device__ int   g_ecol[Ec];
__device__ float g_eval[Ec];                 // PRE-SCALED by DECAY=0.5
__device__ float g_Wkq[Cc*32];               // [j][0:16]=Wk[j][:], [j][16:32]=Wq[j][:]

// ---------------- packed fp32x2 FMA helpers --------------------------------
__device__ __forceinline__ void fma2(unsigned long long& acc,
                                     unsigned long long a,
                                     unsigned long long b) {
    asm("fma.rn.f32x2 %0, %1, %2, %3;" : "=l"(acc) : "l"(a), "l"(b), "l"(acc));
}
__device__ __forceinline__ unsigned long long pack2(float lo, float hi) {
    unsigned long long v;
    asm("mov.b64 %0, {%1,%2};" : "=l"(v) : "f"(lo), "f"(hi));
    return v;
}
__device__ __forceinline__ void unpack2(unsigned long long v, float& lo, float& hi) {
    asm("mov.b64 {%0,%1}, %2;" : "=f"(lo), "=f"(hi) : "l"(v));
}

// ---------------- setup: zero counters + build combined Wkq ----------------
__global__ void setup_kernel(const float* __restrict__ Wk,
                             const float* __restrict__ Wq) {
    int i = blockIdx.x * blockDim.x + threadIdx.x;
    if (i < Gc) g_cnt[i] = 0;
    if (i < Cc * KDc) {
        int j = i >> 4, d = i & 15;
        g_Wkq[j * 32 + d]      = Wk[i];
        g_Wkq[j * 32 + 16 + d] = Wq[i];
    }
}

// ---------------- CSR build -------------------------------------------------
__global__ void count_kernel(const int* __restrict__ erow, int E) {
    int i = (blockIdx.x * blockDim.x + threadIdx.x) * 4;
    if (i + 3 < E) {
        int4 r = *reinterpret_cast<const int4*>(erow + i);
        atomicAdd(&g_cnt[r.x], 1);
        atomicAdd(&g_cnt[r.y], 1);
        atomicAdd(&g_cnt[r.z], 1);
        atomicAdd(&g_cnt[r.w], 1);
    } else {
        for (int k = i; k < E; k++) atomicAdd(&g_cnt[erow[k]], 1);
    }
}

__global__ void scan_kernel() {
    __shared__ int wsum[32];
    __shared__ int carry_s, tot_s;
    int tid = threadIdx.x;
    int wid = tid >> 5, lane = tid & 31;
    if (tid == 0) carry_s = 0;
    __syncthreads();
    for (int base = 0; base < Gc; base += 1024) {
        int idx = base + tid;
        int v = (idx < Gc) ? g_cnt[idx] : 0;
        int inc = v;
        #pragma unroll
        for (int o = 1; o < 32; o <<= 1) {
            int t = __shfl_up_sync(0xffffffffu, inc, o);
            if (lane >= o) inc += t;
        }
        if (lane == 31) wsum[wid] = inc;
        __syncthreads();
        if (wid == 0) {
            int s = wsum[lane];
            int p = s;
            #pragma unroll
            for (int o = 1; o < 32; o <<= 1) {
                int t = __shfl_up_sync(0xffffffffu, p, o);
                if (lane >= o) p += t;
            }
            wsum[lane] = p - s;
            if (lane == 31) tot_s = p;
        }
        __syncthreads();
        if (idx < Gc) {
            int excl = carry_s + wsum[wid] + inc - v;
            g_rowptr[idx] = excl;
            g_fill[idx]   = excl;
        }
        __syncthreads();
        if (tid == 0) carry_s += tot_s;
        __syncthreads();
    }
    if (tid == 0) g_rowptr[Gc] = carry_s;
}

// scatter + pre-scale edge vals by DECAY=0.5 (cur*DECAY then spmm == spmm
// with halved vals; applies identically to both iterations).
__global__ void scatter_kernel(const int* __restrict__ erow,
                               const int* __restrict__ ecol,
                               const float* __restrict__ ev, int E) {
    int i = (blockIdx.x * blockDim.x + threadIdx.x) * 4;
    if (i + 3 < E) {
        int4   r = *reinterpret_cast<const int4*>(erow + i);
        int4   c = *reinterpret_cast<const int4*>(ecol + i);
        float4 v = *reinterpret_cast<const float4*>(ev + i);
        int p;
        p = atomicAdd(&g_fill[r.x], 1); g_ecol[p] = c.x; g_eval[p] = v.x * 0.5f;
        p = atomicAdd(&g_fill[r.y], 1); g_ecol[p] = c.y; g_eval[p] = v.y * 0.5f;
        p = atomicAdd(&g_fill[r.z], 1); g_ecol[p] = c.z; g_eval[p] = v.z * 0.5f;
        p = atomicAdd(&g_fill[r.w], 1); g_ecol[p] = c.w; g_eval[p] = v.w * 0.5f;
    } else {
        for (int k = i; k < E; k++) {
            int p = atomicAdd(&g_fill[erow[k]], 1);
            g_ecol[p] = ecol[k];
            g_eval[p] = ev[k] * 0.5f;
        }
    }
}

// ---------------- weights on x: w[R] = mean_d( (x@Wk)_d * (x@Wq)_d ) --------
// Block = 32 rows. Wkq staged in smem. 8 warps; warp = 4 rows; lane = dim.
__global__ void weightsx_kernel(const float* __restrict__ x) {
    __shared__ __align__(16) float s[32][Cc];
    __shared__ __align__(16) float wkq[Cc * 32];

    int tid = threadIdx.x;                    // 256
    size_t base = (size_t)blockIdx.x * 32 * Cc;
    const float4* gp = reinterpret_cast<const float4*>(x + base);
    float4* sp = reinterpret_cast<float4*>(&s[0][0]);
    const float4* wg = reinterpret_cast<const float4*>(g_Wkq);
    float4* wsp = reinterpret_cast<float4*>(wkq);
    #pragma unroll
    for (int i = 0; i < 4; i++) {
        sp[tid + i * 256]  = gp[tid + i * 256];
        wsp[tid + i * 256] = wg[tid + i * 256];
    }
    __syncthreads();

    int w = tid >> 5, lane = tid & 31;
    const float* r0 = s[w * 4 + 0];
    const float* r1 = s[w * 4 + 1];
    const float* r2 = s[w * 4 + 2];
    const float* r3 = s[w * 4 + 3];

    float a0 = 0.f, a1 = 0.f, a2 = 0.f, a3 = 0.f;
    #pragma unroll 8
    for (int j4 = 0; j4 < Cc / 4; j4++) {
        float4 v0 = *reinterpret_cast<const float4*>(r0 + j4 * 4);
        float4 v1 = *reinterpret_cast<const float4*>(r1 + j4 * 4);
        float4 v2 = *reinterpret_cast<const float4*>(r2 + j4 * 4);
        float4 v3 = *reinterpret_cast<const float4*>(r3 + j4 * 4);
        float w0 = wkq[(j4 * 4 + 0) * 32 + lane];
        float w1 = wkq[(j4 * 4 + 1) * 32 + lane];
        float w2 = wkq[(j4 * 4 + 2) * 32 + lane];
        float w3 = wkq[(j4 * 4 + 3) * 32 + lane];
        a0 += v0.x * w0 + v0.y * w1 + v0.z * w2 + v0.w * w3;
        a1 += v1.x * w0 + v1.y * w1 + v1.z * w2 + v1.w * w3;
        a2 += v2.x * w0 + v2.y * w1 + v2.z * w2 + v2.w * w3;
        a3 += v3.x * w0 + v3.y * w1 + v3.z * w2 + v3.w * w3;
    }

    float p[4];
    p[0] = a0 * __shfl_xor_sync(0xffffffffu, a0, 16);
    p[1] = a1 * __shfl_xor_sync(0xffffffffu, a1, 16);
    p[2] = a2 * __shfl_xor_sync(0xffffffffu, a2, 16);
    p[3] = a3 * __shfl_xor_sync(0xffffffffu, a3, 16);
    #pragma unroll
    for (int r = 0; r < 4; r++) {
        #pragma unroll
        for (int o = 8; o; o >>= 1)
            p[r] += __shfl_xor_sync(0xffffffffu, p[r], o);
    }
    if (lane == 0) {
        int R = blockIdx.x * 32 + w * 4;
        #pragma unroll
        for (int r = 0; r < 4; r++)
            g_weights[R + r] = p[r] * (1.0f / KDc);
    }
}

// ---------------- SPMM + fused weight accumulation --------------------------
// dst[l,g,:] = sum_e val_e * src[l,col_e,:]   (vals pre-scaled by 0.5)
// Epilogue: g_weights[l*Gc+g] += mean_d( (row@Wk)_d * (row@Wq)_d )
__global__ void spmmw_kernel(const float* __restrict__ x, int iter) {
    const float* src = (iter == 0) ? x : g_bufA;
    float* dst       = (iter == 0) ? g_bufA : g_bufB;

    int g = blockIdx.x;
    int t = threadIdx.x;               // 128
    int l  = t >> 5;
    int c4 = (t & 31) * 4;

    int s = g_rowptr[g], e = g_rowptr[g + 1];
    __shared__ int   scol[128];
    __shared__ float sval[128];
    __shared__ __align__(16) float srow[Lc][Cc];   // 2KB result tile

    float4 acc = make_float4(0.f, 0.f, 0.f, 0.f);
    const float* srcb = src + (size_t)l * Gc * Cc + c4;

    for (int base = s; base < e; base += 128) {
        int n = min(128, e - base);
        if (t < n) {
            scol[t] = g_ecol[base + t];
            sval[t] = g_eval[base + t];
        }
        __syncthreads();
        #pragma unroll 8
        for (int i = 0; i < n; i++) {
            float v = sval[i];
            int  cc = scol[i];
            float4 sv = *reinterpret_cast<const float4*>(srcb + (size_t)cc * Cc);
            acc.x += v * sv.x; acc.y += v * sv.y;
            acc.z += v * sv.z; acc.w += v * sv.w;
        }
        __syncthreads();
    }
    // write result + stage for weight epilogue
    *reinterpret_cast<float4*>(dst + ((size_t)l * Gc + g) * Cc + c4) = acc;
    *reinterpret_cast<float4*>(&srow[l][c4]) = acc;
    __syncthreads();

    // weight epilogue: warp w handles plane l=w; lane = combined k/q dim.
    int lane = t & 31;
    const float* sr = srow[l];
    float a = 0.f;
    #pragma unroll 8
    for (int j = 0; j < Cc; j++)
        a += sr[j] * g_Wkq[j * 32 + lane];      // Wkq hot in L1 (16KB)
    float p = a * __shfl_xor_sync(0xffffffffu, a, 16);
    #pragma unroll
    for (int o = 8; o; o >>= 1) p += __shfl_xor_sync(0xffffffffu, p, o);
    if (lane == 0)
        g_weights[l * Gc + g] += p * (1.0f / KDc);
}

// ---------------- final: values = (x+A+B)@Wv, v = values*w, LayerNorm -------
// Block = 32 rows. Wv (64KB) staged into dynamic smem once per block.
__global__ void final3_kernel(const float* __restrict__ x,
                              const float* __restrict__ Wv,
                              const float* __restrict__ gamma,
                              const float* __restrict__ beta,
                              float* __restrict__ out) {
    extern __shared__ __align__(16) float dyn[];
    float* wv_sm = dyn;                 // [128][128]
    float (*s)[Cc] = reinterpret_cast<float(*)[Cc]>(dyn + Cc * Cc);  // [32][128]

    int tid = threadIdx.x;              // 256
    size_t base = (size_t)blockIdx.x * 32 * Cc;

    const float4* wvg = reinterpret_cast<const float4*>(Wv);
    float4* wvs = reinterpret_cast<float4*>(wv_sm);
    #pragma unroll
    for (int i = 0; i < 16; i++) wvs[tid + i * 256] = wvg[tid + i * 256];

    const float4* xp = reinterpret_cast<const float4*>(x + base);
    const float4* ap = reinterpret_cast<const float4*>(g_bufA + base);
    const float4* bp = reinterpret_cast<const float4*>(g_bufB + base);
    float4* sp = reinterpret_cast<float4*>(&s[0][0]);
    #pragma unroll
    for (int i = 0; i < 4; i++) {
        float4 a = xp[tid + i * 256];
        float4 b = ap[tid + i * 256];
        float4 c = bp[tid + i * 256];
        sp[tid + i * 256] = make_float4(a.x + b.x + c.x, a.y + b.y + c.y,
                                        a.z + b.z + c.z, a.w + b.w + c.w);
    }
    __syncthreads();

    int w = tid >> 5, lane = tid & 31;
    const float* r0 = s[w * 4 + 0];
    const float* r1 = s[w * 4 + 1];
    const float* r2 = s[w * 4 + 2];
    const float* r3 = s[w * 4 + 3];

    unsigned long long accA[4] = {0ull, 0ull, 0ull, 0ull};
    unsigned long long accB[4] = {0ull, 0ull, 0ull, 0ull};

    #pragma unroll 4
    for (int j = 0; j < Cc; j++) {
        float4 wv = *reinterpret_cast<const float4*>(wv_sm + j * Cc + lane * 4);
        unsigned long long wlo = pack2(wv.x, wv.y);
        unsigned long long whi = pack2(wv.z, wv.w);
        unsigned long long s0 = pack2(r0[j], r0[j]);
        unsigned long long s1 = pack2(r1[j], r1[j]);
        unsigned long long s2 = pack2(r2[j], r2[j]);
        unsigned long long s3 = pack2(r3[j], r3[j]);
        fma2(accA[0], s0, wlo); fma2(accB[0], s0, whi);
        fma2(accA[1], s1, wlo); fma2(accB[1], s1, whi);
        fma2(accA[2], s2, wlo); fma2(accB[2], s2, whi);
        fma2(accA[3], s3, wlo); fma2(accB[3], s3, whi);
    }

    float4 g4 = reinterpret_cast<const float4*>(gamma)[lane];
    float4 b4 = reinterpret_cast<const float4*>(beta)[lane];
    int Rbase = blockIdx.x * 32 + w * 4;

    #pragma unroll
    for (int r = 0; r < 4; r++) {
        float wt = g_weights[Rbase + r];
        float v0, v1, v2, v3;
        unpack2(accA[r], v0, v1);
        unpack2(accB[r], v2, v3);
        v0 *= wt; v1 *= wt; v2 *= wt; v3 *= wt;

        float t = v0 + v1 + v2 + v3;
        #pragma unroll
        for (int o = 16; o; o >>= 1) t += __shfl_xor_sync(0xffffffffu, t, o);
        float mu = t * (1.0f / Cc);
        float d0 = v0 - mu, d1 = v1 - mu, d2 = v2 - mu, d3 = v3 - mu;
        t = d0 * d0 + d1 * d1 + d2 * d2 + d3 * d3;
        #pragma unroll
        for (int o = 16; o; o >>= 1) t += __shfl_xor_sync(0xffffffffu, t, o);
        float rstd = rsqrtf(t * (1.0f / Cc) + LN_EPS);

        float4 o4 = make_float4(d0 * rstd * g4.x + b4.x,
                                d1 * rstd * g4.y + b4.y,
                                d2 * rstd * g4.z + b4.z,
                                d3 * rstd * g4.w + b4.w);
        reinterpret_cast<float4*>(out)[(size_t)(Rbase + r) * 32 + lane] = o4;
    }
}

// ---------------- launch ----------------------------------------------------
extern "C" void kernel_launch(void* const* d_in, const int* in_sizes, int n_in,
                              void* d_out, int out_size) {
    const float* x     = (const float*)d_in[0];
    const int*   erow  = (const int*)  d_in[1];
    const int*   ecol  = (const int*)  d_in[2];
    const float* evals = (const float*)d_in[3];
    const float* Wk    = (const float*)d_in[4];
    const float* Wq    = (const float*)d_in[5];
    const float* Wv    = (const float*)d_in[6];
    const float* gamma = (const float*)d_in[7];
    const float* beta  = (const float*)d_in[8];
    float* out = (float*)d_out;
    int E = in_sizes[1];
    if (E > Ec) E = Ec;

    setup_kernel<<<(Gc + 255) / 256, 256>>>(Wk, Wq);
    int eblk = ((E + 3) / 4 + 255) / 256;
    count_kernel<<<eblk, 256>>>(erow, E);
    scan_kernel<<<1, 1024>>>();
    scatter_kernel<<<eblk, 256>>>(erow, ecol, evals, E);

    const int WBLOCKS = NROWS / 32;   // 2500

    weightsx_kernel<<<WBLOCKS, 256>>>(x);       // initializes g_weights
    spmmw_kernel<<<Gc, 128>>>(x, 0);            // A + weight accum
    spmmw_kernel<<<Gc, 128>>>(x, 1);            // B + weight accum

    static const int FINAL_SMEM = (Cc * Cc + 32 * Cc) * sizeof(float); // 80KB
    cudaFuncSetAttribute(final3_kernel,
                         cudaFuncAttributeMaxDynamicSharedMemorySize, FINAL_SMEM);
    final3_kernel<<<WBLOCKS, 256, FINAL_SMEM>>>(x, Wv, gamma, beta, out);
}

// round 7
// speedup vs baseline: 1.2226x; 1.2226x over previous
#include <cuda_runtime.h>
#include <cstdint>

// Problem constants (match reference)
#define Lc 4
#define Gc 20000
#define Cc 128
#define Ec 320000
#define KDc 16
#define NROWS (Lc*Gc)          // 80000 state rows of length 128
#define LN_EPS 1e-5f

typedef unsigned long long u64;

// ---------------- device scratch (static: no allocation APIs) --------------
__device__ float g_bufA[(size_t)Lc*Gc*Cc];   // xr1
__device__ float g_bufB[(size_t)Lc*Gc*Cc];   // xr2
__device__ float g_weights[NROWS];           // flat index R = l*Gc + g
__device__ int   g_rowptr[Gc+1];
__device__ int   g_cnt[Gc];
__device__ int   g_fill[Gc];
__device__ int   g_ecol[Ec];
__device__ float g_eval[Ec];                 // PRE-SCALED by DECAY=0.5
// paired layout: g_Wkq2[(j2*32+d)*2 + {0,1}] = W(2*j2, d), W(2*j2+1, d)
// where W(j,d) = Wk[j][d] for d<16 else Wq[j][d-16]
__device__ float g_Wkq2[(Cc/2)*32*2];

// ---------------- packed fp32x2 FMA helpers --------------------------------
__device__ __forceinline__ void fma2(u64& acc, u64 a, u64 b) {
    asm("fma.rn.f32x2 %0, %1, %2, %3;" : "=l"(acc) : "l"(a), "l"(b), "l"(acc));
}
__device__ __forceinline__ u64 pack2(float lo, float hi) {
    u64 v;
    asm("mov.b64 %0, {%1,%2};" : "=l"(v) : "f"(lo), "f"(hi));
    return v;
}
__device__ __forceinline__ void unpack2(u64 v, float& lo, float& hi) {
    asm("mov.b64 {%0,%1}, %2;" : "=f"(lo), "=f"(hi) : "l"(v));
}

// ---------------- setup: zero counters + build paired Wkq2 -----------------
__global__ void setup_kernel(const float* __restrict__ Wk,
                             const float* __restrict__ Wq) {
    int i = blockIdx.x * blockDim.x + threadIdx.x;
    if (i < Gc) g_cnt[i] = 0;
    if (i < (Cc / 2) * 32) {
        int j2 = i >> 5, d = i & 31;
        const float* W = (d < 16) ? Wk : Wq;
        int dd = d & 15;
        g_Wkq2[i * 2 + 0] = W[(2 * j2 + 0) * KDc + dd];
        g_Wkq2[i * 2 + 1] = W[(2 * j2 + 1) * KDc + dd];
    }
}

// ---------------- CSR build -------------------------------------------------
__global__ void count_kernel(const int* __restrict__ erow, int E) {
    int i = (blockIdx.x * blockDim.x + threadIdx.x) * 4;
    if (i + 3 < E) {
        int4 r = *reinterpret_cast<const int4*>(erow + i);
        atomicAdd(&g_cnt[r.x], 1);
        atomicAdd(&g_cnt[r.y], 1);
        atomicAdd(&g_cnt[r.z], 1);
        atomicAdd(&g_cnt[r.w], 1);
    } else {
        for (int k = i; k < E; k++) atomicAdd(&g_cnt[erow[k]], 1);
    }
}

__global__ void scan_kernel() {
    __shared__ int wsum[32];
    __shared__ int carry_s, tot_s;
    int tid = threadIdx.x;
    int wid = tid >> 5, lane = tid & 31;
    if (tid == 0) carry_s = 0;
    __syncthreads();
    for (int base = 0; base < Gc; base += 1024) {
        int idx = base + tid;
        int v = (idx < Gc) ? g_cnt[idx] : 0;
        int inc = v;
        #pragma unroll
        for (int o = 1; o < 32; o <<= 1) {
            int t = __shfl_up_sync(0xffffffffu, inc, o);
            if (lane >= o) inc += t;
        }
        if (lane == 31) wsum[wid] = inc;
        __syncthreads();
        if (wid == 0) {
            int s = wsum[lane];
            int p = s;
            #pragma unroll
            for (int o = 1; o < 32; o <<= 1) {
                int t = __shfl_up_sync(0xffffffffu, p, o);
                if (lane >= o) p += t;
            }
            wsum[lane] = p - s;
            if (lane == 31) tot_s = p;
        }
        __syncthreads();
        if (idx < Gc) {
            int excl = carry_s + wsum[wid] + inc - v;
            g_rowptr[idx] = excl;
            g_fill[idx]   = excl;
        }
        __syncthreads();
        if (tid == 0) carry_s += tot_s;
        __syncthreads();
    }
    if (tid == 0) g_rowptr[Gc] = carry_s;
}

// scatter + pre-scale edge vals by DECAY=0.5
__global__ void scatter_kernel(const int* __restrict__ erow,
                               const int* __restrict__ ecol,
                               const float* __restrict__ ev, int E) {
    int i = (blockIdx.x * blockDim.x + threadIdx.x) * 4;
    if (i + 3 < E) {
        int4   r = *reinterpret_cast<const int4*>(erow + i);
        int4   c = *reinterpret_cast<const int4*>(ecol + i);
        float4 v = *reinterpret_cast<const float4*>(ev + i);
        int p;
        p = atomicAdd(&g_fill[r.x], 1); g_ecol[p] = c.x; g_eval[p] = v.x * 0.5f;
        p = atomicAdd(&g_fill[r.y], 1); g_ecol[p] = c.y; g_eval[p] = v.y * 0.5f;
        p = atomicAdd(&g_fill[r.z], 1); g_ecol[p] = c.z; g_eval[p] = v.z * 0.5f;
        p = atomicAdd(&g_fill[r.w], 1); g_ecol[p] = c.w; g_eval[p] = v.w * 0.5f;
    } else {
        for (int k = i; k < E; k++) {
            int p = atomicAdd(&g_fill[erow[k]], 1);
            g_ecol[p] = ecol[k];
            g_eval[p] = ev[k] * 0.5f;
        }
    }
}

// ---------------- fused launch: SPMM blocks + weights blocks ----------------
// blocks [0, Gc/2):       spmm, warp-autonomous: warp w -> g = 2b + (w>>2),
//                         l = w&3. dst[l,g,:] = sum_e val_e * src[l,col_e,:]
// blocks [Gc/2, Gc/2+2500): weights pass over 32 state rows each:
//                         iter==0: g_weights = wproj(x)   (init)
//                         iter==1: g_weights += wproj(A)  (accumulate)
#define SPMM_BLOCKS (Gc/2)
#define WT_BLOCKS   (NROWS/32)

__global__ void fused_kernel(const float* __restrict__ x, int iter) {
    if (blockIdx.x < SPMM_BLOCKS) {
        const float* src = (iter == 0) ? x : g_bufA;
        float* dst       = (iter == 0) ? g_bufA : g_bufB;
        int w = threadIdx.x >> 5, lane = threadIdx.x & 31;
        int g = blockIdx.x * 2 + (w >> 2);
        int l = w & 3;
        int s = g_rowptr[g], e = g_rowptr[g + 1];
        const float* srcb = src + (size_t)l * Gc * Cc + lane * 4;
        float4 acc = make_float4(0.f, 0.f, 0.f, 0.f);
        for (int base = s; base < e; base += 32) {
            int n = min(32, e - base);
            int col = 0; float val = 0.f;
            if (lane < n) {
                col = g_ecol[base + lane];
                val = g_eval[base + lane];
            }
            #pragma unroll 4
            for (int i = 0; i < n; i++) {
                int   cc = __shfl_sync(0xffffffffu, col, i);
                float v  = __shfl_sync(0xffffffffu, val, i);
                float4 sv = *reinterpret_cast<const float4*>(srcb + (size_t)cc * Cc);
                acc.x += v * sv.x; acc.y += v * sv.y;
                acc.z += v * sv.z; acc.w += v * sv.w;
            }
        }
        *reinterpret_cast<float4*>(dst + ((size_t)l * Gc + g) * Cc + lane * 4) = acc;
    } else {
        // ---- weights pass: 32 rows, 8 warps x 4 rows, lane = kq dim ----
        __shared__ __align__(16) float s[32][Cc];
        __shared__ __align__(16) float wkq2[(Cc/2)*32*2];
        int b = blockIdx.x - SPMM_BLOCKS;
        const float* state = (iter == 0) ? x : g_bufA;
        int tid = threadIdx.x;                    // 256

        const float4* gp = reinterpret_cast<const float4*>(state + (size_t)b * 32 * Cc);
        float4* sp = reinterpret_cast<float4*>(&s[0][0]);
        const float4* wg = reinterpret_cast<const float4*>(g_Wkq2);
        float4* wsp = reinterpret_cast<float4*>(wkq2);
        #pragma unroll
        for (int i = 0; i < 4; i++) {
            sp[tid + i * 256]  = gp[tid + i * 256];
            wsp[tid + i * 256] = wg[tid + i * 256];
        }
        __syncthreads();

        int w = tid >> 5, lane = tid & 31;
        u64 acc[4] = {0ull, 0ull, 0ull, 0ull};
        #pragma unroll 8
        for (int j2 = 0; j2 < Cc / 2; j2++) {
            u64 w2 = *reinterpret_cast<const u64*>(wkq2 + (j2 * 32 + lane) * 2);
            #pragma unroll
            for (int r = 0; r < 4; r++) {
                u64 sv = *reinterpret_cast<const u64*>(&s[w * 4 + r][j2 * 2]);
                fma2(acc[r], sv, w2);
            }
        }
        #pragma unroll
        for (int r = 0; r < 4; r++) {
            float lo, hi;
            unpack2(acc[r], lo, hi);
            float a = lo + hi;
            float p = a * __shfl_xor_sync(0xffffffffu, a, 16);
            #pragma unroll
            for (int o = 8; o; o >>= 1)
                p += __shfl_xor_sync(0xffffffffu, p, o);
            if (lane == 0) {
                int R = b * 32 + w * 4 + r;
                float val = p * (1.0f / KDc);
                g_weights[R] = iter ? (g_weights[R] + val) : val;
            }
        }
    }
}

// ---------------- final: wB + (x+A+B)@Wv * w + LayerNorm --------------------
// Block = 64 rows, 8 warps x 8 rows, lane = 4 output cols.
// Prologue computes this block's weight(B) contribution from the staged B tile.
__global__ void __launch_bounds__(256, 2)
final5_kernel(const float* __restrict__ x,
              const float* __restrict__ Wv,
              const float* __restrict__ gamma,
              const float* __restrict__ beta,
              float* __restrict__ out) {
    extern __shared__ __align__(16) float dyn[];
    float* wv_sm = dyn;                                    // [128][128] 64KB
    float (*s)[Cc] = reinterpret_cast<float(*)[Cc]>(dyn + Cc * Cc);  // [64][128] 32KB

    int tid = threadIdx.x;              // 256
    size_t base = (size_t)blockIdx.x * 64 * Cc;

    // stage Wv (64KB) + B tile (32KB)
    const float4* wvg = reinterpret_cast<const float4*>(Wv);
    float4* wvs = reinterpret_cast<float4*>(wv_sm);
    #pragma unroll
    for (int i = 0; i < 16; i++) wvs[tid + i * 256] = wvg[tid + i * 256];
    const float4* bp = reinterpret_cast<const float4*>(g_bufB + base);
    float4* sp = reinterpret_cast<float4*>(&s[0][0]);
    #pragma unroll
    for (int i = 0; i < 8; i++) sp[tid + i * 256] = bp[tid + i * 256];
    __syncthreads();

    int w = tid >> 5, lane = tid & 31;
    int row0 = w * 8;

    // ---- weight(B) contribution for this warp's 8 rows ----
    float wB[8];
    {
        u64 acc[8] = {0ull,0ull,0ull,0ull,0ull,0ull,0ull,0ull};
        #pragma unroll 4
        for (int j2 = 0; j2 < Cc / 2; j2++) {
            u64 w2 = *reinterpret_cast<const u64*>(g_Wkq2 + (j2 * 32 + lane) * 2);
            #pragma unroll
            for (int r = 0; r < 8; r++) {
                u64 sv = *reinterpret_cast<const u64*>(&s[row0 + r][j2 * 2]);
                fma2(acc[r], sv, w2);
            }
        }
        #pragma unroll
        for (int r = 0; r < 8; r++) {
            float lo, hi;
            unpack2(acc[r], lo, hi);
            float a = lo + hi;
            float p = a * __shfl_xor_sync(0xffffffffu, a, 16);
            #pragma unroll
            for (int o = 8; o; o >>= 1)
                p += __shfl_xor_sync(0xffffffffu, p, o);
            wB[r] = p * (1.0f / KDc);
        }
    }
    __syncthreads();                    // everyone done reading B tile

    // ---- s = B + x + A ----
    const float4* xp = reinterpret_cast<const float4*>(x + base);
    const float4* ap = reinterpret_cast<const float4*>(g_bufA + base);
    #pragma unroll
    for (int i = 0; i < 8; i++) {
        float4 a = xp[tid + i * 256];
        float4 b = ap[tid + i * 256];
        float4 c = sp[tid + i * 256];
        sp[tid + i * 256] = make_float4(a.x + b.x + c.x, a.y + b.y + c.y,
                                        a.z + b.z + c.z, a.w + b.w + c.w);
    }
    __syncthreads();

    // ---- GEMM: 8 rows/warp, cols lane*4..lane*4+3, j4-blocked ----
    u64 accA[8] = {0ull,0ull,0ull,0ull,0ull,0ull,0ull,0ull};
    u64 accB[8] = {0ull,0ull,0ull,0ull,0ull,0ull,0ull,0ull};
    #pragma unroll 2
    for (int j4 = 0; j4 < Cc / 4; j4++) {
        float4 wv0 = *reinterpret_cast<const float4*>(wv_sm + (j4*4+0)*Cc + lane*4);
        float4 wv1 = *reinterpret_cast<const float4*>(wv_sm + (j4*4+1)*Cc + lane*4);
        float4 wv2 = *reinterpret_cast<const float4*>(wv_sm + (j4*4+2)*Cc + lane*4);
        float4 wv3 = *reinterpret_cast<const float4*>(wv_sm + (j4*4+3)*Cc + lane*4);
        u64 wlo0 = pack2(wv0.x, wv0.y), whi0 = pack2(wv0.z, wv0.w);
        u64 wlo1 = pack2(wv1.x, wv1.y), whi1 = pack2(wv1.z, wv1.w);
        u64 wlo2 = pack2(wv2.x, wv2.y), whi2 = pack2(wv2.z, wv2.w);
        u64 wlo3 = pack2(wv3.x, wv3.y), whi3 = pack2(wv3.z, wv3.w);
        #pragma unroll
        for (int r = 0; r < 8; r++) {
            float4 f = *reinterpret_cast<const float4*>(&s[row0 + r][j4 * 4]);
            u64 f0 = pack2(f.x, f.x), f1 = pack2(f.y, f.y);
            u64 f2 = pack2(f.z, f.z), f3 = pack2(f.w, f.w);
            fma2(accA[r], f0, wlo0); fma2(accB[r], f0, whi0);
            fma2(accA[r], f1, wlo1); fma2(accB[r], f1, whi1);
            fma2(accA[r], f2, wlo2); fma2(accB[r], f2, whi2);
            fma2(accA[r], f3, wlo3); fma2(accB[r], f3, whi3);
        }
    }

    // ---- scale + LayerNorm + write ----
    float4 g4 = reinterpret_cast<const float4*>(gamma)[lane];
    float4 b4 = reinterpret_cast<const float4*>(beta)[lane];
    int Rbase = blockIdx.x * 64 + row0;

    #pragma unroll
    for (int r = 0; r < 8; r++) {
        float wt = g_weights[Rbase + r] + wB[r];
        float v0, v1, v2, v3;
        unpack2(accA[r], v0, v1);
        unpack2(accB[r], v2, v3);
        v0 *= wt; v1 *= wt; v2 *= wt; v3 *= wt;

        float t = v0 + v1 + v2 + v3;
        #pragma unroll
        for (int o = 16; o; o >>= 1) t += __shfl_xor_sync(0xffffffffu, t, o);
        float mu = t * (1.0f / Cc);
        float d0 = v0 - mu, d1 = v1 - mu, d2 = v2 - mu, d3 = v3 - mu;
        t = d0 * d0 + d1 * d1 + d2 * d2 + d3 * d3;
        #pragma unroll
        for (int o = 16; o; o >>= 1) t += __shfl_xor_sync(0xffffffffu, t, o);
        float rstd = rsqrtf(t * (1.0f / Cc) + LN_EPS);

        float4 o4 = make_float4(d0 * rstd * g4.x + b4.x,
                                d1 * rstd * g4.y + b4.y,
                                d2 * rstd * g4.z + b4.z,
                                d3 * rstd * g4.w + b4.w);
        reinterpret_cast<float4*>(out)[(size_t)(Rbase + r) * 32 + lane] = o4;
    }
}

// ---------------- launch ----------------------------------------------------
extern "C" void kernel_launch(void* const* d_in, const int* in_sizes, int n_in,
                              void* d_out, int out_size) {
    const float* x     = (const float*)d_in[0];
    const int*   erow  = (const int*)  d_in[1];
    const int*   ecol  = (const int*)  d_in[2];
    const float* evals = (const float*)d_in[3];
    const float* Wk    = (const float*)d_in[4];
    const float* Wq    = (const float*)d_in[5];
    const float* Wv    = (const float*)d_in[6];
    const float* gamma = (const float*)d_in[7];
    const float* beta  = (const float*)d_in[8];
    float* out = (float*)d_out;
    int E = in_sizes[1];
    if (E > Ec) E = Ec;

    setup_kernel<<<(Gc + 255) / 256, 256>>>(Wk, Wq);
    int eblk = ((E + 3) / 4 + 255) / 256;
    count_kernel<<<eblk, 256>>>(erow, E);
    scan_kernel<<<1, 1024>>>();
    scatter_kernel<<<eblk, 256>>>(erow, ecol, evals, E);

    // fused: spmm (10000 blocks) + weights pass (2500 blocks), one launch each
    fused_kernel<<<SPMM_BLOCKS + WT_BLOCKS, 256>>>(x, 0);  // A + w(x) init
    fused_kernel<<<SPMM_BLOCKS + WT_BLOCKS, 256>>>(x, 1);  // B + w(A) accum

    // final: wB prologue + GEMM + scale + LayerNorm
    static const int FINAL_SMEM = (Cc * Cc + 64 * Cc) * sizeof(float); // 96KB
    cudaFuncSetAttribute(final5_kernel,
                         cudaFuncAttributeMaxDynamicSharedMemorySize, FINAL_SMEM);
    final5_kernel<<<NROWS / 64, 256, FINAL_SMEM>>>(x, Wv, gamma, beta, out);
}

// round 8
// speedup vs baseline: 1.2301x; 1.0061x over previous
#include <cuda_runtime.h>
#include <cstdint>

// Problem constants (match reference)
#define Lc 4
#define Gc 20000
#define Cc 128
#define Ec 320000
#define KDc 16
#define NROWS (Lc*Gc)          // 80000 state rows of length 128
#define LN_EPS 1e-5f

typedef unsigned long long u64;

#define WT_BLOCKS   (NROWS/32)   // 2500
#define SPMM_BLOCKS (Gc/2)       // 10000

// ---------------- device scratch (static: no allocation APIs) --------------
__device__ float g_bufA[(size_t)Lc*Gc*Cc];   // xr1
__device__ float g_bufB[(size_t)Lc*Gc*Cc];   // xr2
__device__ float g_weights[NROWS];           // flat index R = l*Gc + g
__device__ int   g_rowptr[Gc+1];
__device__ int   g_cnt[Gc];
__device__ int   g_fill[Gc];
__device__ int2  g_edge[Ec];                 // (col, __float_as_int(val*0.5))
// paired layout: g_Wkq2[(j2*32+d)*2 + {0,1}] = W(2*j2, d), W(2*j2+1, d)
// where W(j,d) = Wk[j][d] for d<16 else Wq[j][d-16]
__device__ float g_Wkq2[(Cc/2)*32*2];

// ---------------- packed fp32x2 FMA helpers --------------------------------
__device__ __forceinline__ void fma2(u64& acc, u64 a, u64 b) {
    asm("fma.rn.f32x2 %0, %1, %2, %3;" : "=l"(acc) : "l"(a), "l"(b), "l"(acc));
}
__device__ __forceinline__ u64 pack2(float lo, float hi) {
    u64 v;
    asm("mov.b64 %0, {%1,%2};" : "=l"(v) : "f"(lo), "f"(hi));
    return v;
}
__device__ __forceinline__ void unpack2(u64 v, float& lo, float& hi) {
    asm("mov.b64 {%0,%1}, %2;" : "=f"(lo), "=f"(hi) : "l"(v));
}

// ---------------- setup: zero counters + build paired Wkq2 -----------------
__global__ void setup_kernel(const float* __restrict__ Wk,
                             const float* __restrict__ Wq) {
    int i = blockIdx.x * blockDim.x + threadIdx.x;
    if (i < Gc) g_cnt[i] = 0;
    if (i < (Cc / 2) * 32) {
        int j2 = i >> 5, d = i & 31;
        const float* W = (d < 16) ? Wk : Wq;
        int dd = d & 15;
        g_Wkq2[i * 2 + 0] = W[(2 * j2 + 0) * KDc + dd];
        g_Wkq2[i * 2 + 1] = W[(2 * j2 + 1) * KDc + dd];
    }
}

// ---------------- CSR build -------------------------------------------------
__global__ void count_kernel(const int* __restrict__ erow, int E) {
    int i = (blockIdx.x * blockDim.x + threadIdx.x) * 4;
    if (i + 3 < E) {
        int4 r = *reinterpret_cast<const int4*>(erow + i);
        atomicAdd(&g_cnt[r.x], 1);
        atomicAdd(&g_cnt[r.y], 1);
        atomicAdd(&g_cnt[r.z], 1);
        atomicAdd(&g_cnt[r.w], 1);
    } else {
        for (int k = i; k < E; k++) atomicAdd(&g_cnt[erow[k]], 1);
    }
}

// ---------------- scan (block 0) + weights(x) init (blocks 1..2500) ---------
// 1024 threads. Weights blocks: 32 warps, warp w = tile row w, lane = kq dim.
__global__ void scan_wx_kernel(const float* __restrict__ x) {
    __shared__ __align__(16) float sm[32][Cc];      // 16KB (weights) / reuse
    __shared__ __align__(16) float wkq2[(Cc/2)*32*2]; // 16KB
    __shared__ int wsum[32];
    __shared__ int carry_s, tot_s;

    int tid = threadIdx.x;
    int wid = tid >> 5, lane = tid & 31;

    if (blockIdx.x == 0) {
        // ---------------- serial scan over g_cnt ----------------
        if (tid == 0) carry_s = 0;
        __syncthreads();
        for (int base = 0; base < Gc; base += 1024) {
            int idx = base + tid;
            int v = (idx < Gc) ? g_cnt[idx] : 0;
            int inc = v;
            #pragma unroll
            for (int o = 1; o < 32; o <<= 1) {
                int t = __shfl_up_sync(0xffffffffu, inc, o);
                if (lane >= o) inc += t;
            }
            if (lane == 31) wsum[wid] = inc;
            __syncthreads();
            if (wid == 0) {
                int s = wsum[lane];
                int p = s;
                #pragma unroll
                for (int o = 1; o < 32; o <<= 1) {
                    int t = __shfl_up_sync(0xffffffffu, p, o);
                    if (lane >= o) p += t;
                }
                wsum[lane] = p - s;
                if (lane == 31) tot_s = p;
            }
            __syncthreads();
            if (idx < Gc) {
                int excl = carry_s + wsum[wid] + inc - v;
                g_rowptr[idx] = excl;
                g_fill[idx]   = excl;
            }
            __syncthreads();
            if (tid == 0) carry_s += tot_s;
            __syncthreads();
        }
        if (tid == 0) g_rowptr[Gc] = carry_s;
    } else {
        // ---------------- weights(x) init for tile b ----------------
        int b = blockIdx.x - 1;
        const float4* gp = reinterpret_cast<const float4*>(x + (size_t)b * 32 * Cc);
        float4* sp = reinterpret_cast<float4*>(&sm[0][0]);
        const float4* wg = reinterpret_cast<const float4*>(g_Wkq2);
        float4* wsp = reinterpret_cast<float4*>(wkq2);
        sp[tid]  = gp[tid];          // 1024 float4 = full 16KB tile
        wsp[tid] = wg[tid];
        __syncthreads();

        // warp wid handles row wid; lane = combined k/q dim
        u64 acc0 = 0ull, acc1 = 0ull;
        const float* sr = sm[wid];
        #pragma unroll 8
        for (int j2 = 0; j2 < Cc / 2; j2 += 2) {
            u64 w2a = *reinterpret_cast<const u64*>(wkq2 + (j2 * 32 + lane) * 2);
            u64 w2b = *reinterpret_cast<const u64*>(wkq2 + ((j2 + 1) * 32 + lane) * 2);
            u64 sa  = *reinterpret_cast<const u64*>(sr + j2 * 2);
            u64 sb  = *reinterpret_cast<const u64*>(sr + j2 * 2 + 2);
            fma2(acc0, sa, w2a);
            fma2(acc1, sb, w2b);
        }
        float l0, h0, l1, h1;
        unpack2(acc0, l0, h0);
        unpack2(acc1, l1, h1);
        float a = (l0 + h0) + (l1 + h1);
        float p = a * __shfl_xor_sync(0xffffffffu, a, 16);
        #pragma unroll
        for (int o = 8; o; o >>= 1) p += __shfl_xor_sync(0xffffffffu, p, o);
        if (lane == 0)
            g_weights[b * 32 + wid] = p * (1.0f / KDc);
    }
}

// ---------------- scatter: build packed (col, val*0.5) edge list ------------
__global__ void scatter_kernel(const int* __restrict__ erow,
                               const int* __restrict__ ecol,
                               const float* __restrict__ ev, int E) {
    int i = (blockIdx.x * blockDim.x + threadIdx.x) * 4;
    if (i + 3 < E) {
        int4   r = *reinterpret_cast<const int4*>(erow + i);
        int4   c = *reinterpret_cast<const int4*>(ecol + i);
        float4 v = *reinterpret_cast<const float4*>(ev + i);
        int p;
        p = atomicAdd(&g_fill[r.x], 1); g_edge[p] = make_int2(c.x, __float_as_int(v.x * 0.5f));
        p = atomicAdd(&g_fill[r.y], 1); g_edge[p] = make_int2(c.y, __float_as_int(v.y * 0.5f));
        p = atomicAdd(&g_fill[r.z], 1); g_edge[p] = make_int2(c.z, __float_as_int(v.z * 0.5f));
        p = atomicAdd(&g_fill[r.w], 1); g_edge[p] = make_int2(c.w, __float_as_int(v.w * 0.5f));
    } else {
        for (int k = i; k < E; k++) {
            int p = atomicAdd(&g_fill[erow[k]], 1);
            g_edge[p] = make_int2(ecol[k], __float_as_int(ev[k] * 0.5f));
        }
    }
}

// ---------------- spmm core (warp-autonomous, uniform edge loads) -----------
__device__ __forceinline__ void spmm_warp(const float* __restrict__ src,
                                          float* __restrict__ dst,
                                          int g, int l, int lane) {
    int s = g_rowptr[g], e = g_rowptr[g + 1];
    const float* srcb = src + (size_t)l * Gc * Cc + lane * 4;
    float4 acc = make_float4(0.f, 0.f, 0.f, 0.f);
    #pragma unroll 4
    for (int k = s; k < e; k++) {
        int2 cv = g_edge[k];                    // uniform LDG.64 (L1-shared)
        float v = __int_as_float(cv.y);
        float4 sv = *reinterpret_cast<const float4*>(srcb + (size_t)cv.x * Cc);
        acc.x += v * sv.x; acc.y += v * sv.y;
        acc.z += v * sv.z; acc.w += v * sv.w;
    }
    *reinterpret_cast<float4*>(dst + ((size_t)l * Gc + g) * Cc + lane * 4) = acc;
}

// ---------------- spmm1: x -> A (pure gather launch) ------------------------
__global__ void spmm1_kernel(const float* __restrict__ x) {
    int w = threadIdx.x >> 5, lane = threadIdx.x & 31;
    int g = blockIdx.x * 2 + (w >> 2);
    spmm_warp(x, g_bufA, g, w & 3, lane);
}

// ---------------- spmm2 + weights(A): weights blocks FIRST ------------------
__global__ void spmm2_kernel() {
    if (blockIdx.x >= WT_BLOCKS) {
        int b = blockIdx.x - WT_BLOCKS;
        int w = threadIdx.x >> 5, lane = threadIdx.x & 31;
        int g = b * 2 + (w >> 2);
        spmm_warp(g_bufA, g_bufB, g, w & 3, lane);
    } else {
        // weights(A) accumulate: 32 rows, 8 warps x 4 rows, lane = kq dim
        __shared__ __align__(16) float s[32][Cc];
        __shared__ __align__(16) float wkq2[(Cc/2)*32*2];
        int b = blockIdx.x;
        int tid = threadIdx.x;                    // 256

        const float4* gp = reinterpret_cast<const float4*>(g_bufA + (size_t)b * 32 * Cc);
        float4* sp = reinterpret_cast<float4*>(&s[0][0]);
        const float4* wg = reinterpret_cast<const float4*>(g_Wkq2);
        float4* wsp = reinterpret_cast<float4*>(wkq2);
        #pragma unroll
        for (int i = 0; i < 4; i++) {
            sp[tid + i * 256]  = gp[tid + i * 256];
            wsp[tid + i * 256] = wg[tid + i * 256];
        }
        __syncthreads();

        int w = tid >> 5, lane = tid & 31;
        u64 acc[4] = {0ull, 0ull, 0ull, 0ull};
        #pragma unroll 8
        for (int j2 = 0; j2 < Cc / 2; j2++) {
            u64 w2 = *reinterpret_cast<const u64*>(wkq2 + (j2 * 32 + lane) * 2);
            #pragma unroll
            for (int r = 0; r < 4; r++) {
                u64 sv = *reinterpret_cast<const u64*>(&s[w * 4 + r][j2 * 2]);
                fma2(acc[r], sv, w2);
            }
        }
        #pragma unroll
        for (int r = 0; r < 4; r++) {
            float lo, hi;
            unpack2(acc[r], lo, hi);
            float a = lo + hi;
            float p = a * __shfl_xor_sync(0xffffffffu, a, 16);
            #pragma unroll
            for (int o = 8; o; o >>= 1)
                p += __shfl_xor_sync(0xffffffffu, p, o);
            if (lane == 0) {
                int R = b * 32 + w * 4 + r;
                g_weights[R] += p * (1.0f / KDc);
            }
        }
    }
}

// ---------------- final: wB + (x+A+B)@Wv * w + LayerNorm --------------------
// Block = 64 rows, 8 warps x 8 rows, lane = 4 output cols.
__global__ void __launch_bounds__(256, 2)
final5_kernel(const float* __restrict__ x,
              const float* __restrict__ Wv,
              const float* __restrict__ gamma,
              const float* __restrict__ beta,
              float* __restrict__ out) {
    extern __shared__ __align__(16) float dyn[];
    float* wv_sm = dyn;                                    // [128][128] 64KB
    float (*s)[Cc] = reinterpret_cast<float(*)[Cc]>(dyn + Cc * Cc);  // [64][128] 32KB

    int tid = threadIdx.x;              // 256
    size_t base = (size_t)blockIdx.x * 64 * Cc;

    // stage Wv (64KB) + B tile (32KB)
    const float4* wvg = reinterpret_cast<const float4*>(Wv);
    float4* wvs = reinterpret_cast<float4*>(wv_sm);
    #pragma unroll
    for (int i = 0; i < 16; i++) wvs[tid + i * 256] = wvg[tid + i * 256];
    const float4* bp = reinterpret_cast<const float4*>(g_bufB + base);
    float4* sp = reinterpret_cast<float4*>(&s[0][0]);
    #pragma unroll
    for (int i = 0; i < 8; i++) sp[tid + i * 256] = bp[tid + i * 256];
    __syncthreads();

    int w = tid >> 5, lane = tid & 31;
    int row0 = w * 8;

    // ---- weight(B) contribution for this warp's 8 rows ----
    float wB[8];
    {
        u64 acc[8] = {0ull,0ull,0ull,0ull,0ull,0ull,0ull,0ull};
        #pragma unroll 4
        for (int j2 = 0; j2 < Cc / 2; j2++) {
            u64 w2 = *reinterpret_cast<const u64*>(g_Wkq2 + (j2 * 32 + lane) * 2);
            #pragma unroll
            for (int r = 0; r < 8; r++) {
                u64 sv = *reinterpret_cast<const u64*>(&s[row0 + r][j2 * 2]);
                fma2(acc[r], sv, w2);
            }
        }
        #pragma unroll
        for (int r = 0; r < 8; r++) {
            float lo, hi;
            unpack2(acc[r], lo, hi);
            float a = lo + hi;
            float p = a * __shfl_xor_sync(0xffffffffu, a, 16);
            #pragma unroll
            for (int o = 8; o; o >>= 1)
                p += __shfl_xor_sync(0xffffffffu, p, o);
            wB[r] = p * (1.0f / KDc);
        }
    }
    __syncthreads();                    // everyone done reading B tile

    // ---- s = B + x + A ----
    const float4* xp = reinterpret_cast<const float4*>(x + base);
    const float4* ap = reinterpret_cast<const float4*>(g_bufA + base);
    #pragma unroll
    for (int i = 0; i < 8; i++) {
        float4 a = xp[tid + i * 256];
        float4 b = ap[tid + i * 256];
        float4 c = sp[tid + i * 256];
        sp[tid + i * 256] = make_float4(a.x + b.x + c.x, a.y + b.y + c.y,
                                        a.z + b.z + c.z, a.w + b.w + c.w);
    }
    __syncthreads();

    // ---- GEMM: 8 rows/warp, cols lane*4..lane*4+3, j4-blocked ----
    u64 accA[8] = {0ull,0ull,0ull,0ull,0ull,0ull,0ull,0ull};
    u64 accB[8] = {0ull,0ull,0ull,0ull,0ull,0ull,0ull,0ull};
    #pragma unroll 2
    for (int j4 = 0; j4 < Cc / 4; j4++) {
        float4 wv0 = *reinterpret_cast<const float4*>(wv_sm + (j4*4+0)*Cc + lane*4);
        float4 wv1 = *reinterpret_cast<const float4*>(wv_sm + (j4*4+1)*Cc + lane*4);
        float4 wv2 = *reinterpret_cast<const float4*>(wv_sm + (j4*4+2)*Cc + lane*4);
        float4 wv3 = *reinterpret_cast<const float4*>(wv_sm + (j4*4+3)*Cc + lane*4);
        u64 wlo0 = pack2(wv0.x, wv0.y), whi0 = pack2(wv0.z, wv0.w);
        u64 wlo1 = pack2(wv1.x, wv1.y), whi1 = pack2(wv1.z, wv1.w);
        u64 wlo2 = pack2(wv2.x, wv2.y), whi2 = pack2(wv2.z, wv2.w);
        u64 wlo3 = pack2(wv3.x, wv3.y), whi3 = pack2(wv3.z, wv3.w);
        #pragma unroll
        for (int r = 0; r < 8; r++) {
            float4 f = *reinterpret_cast<const float4*>(&s[row0 + r][j4 * 4]);
            u64 f0 = pack2(f.x, f.x), f1 = pack2(f.y, f.y);
            u64 f2 = pack2(f.z, f.z), f3 = pack2(f.w, f.w);
            fma2(accA[r], f0, wlo0); fma2(accB[r], f0, whi0);
            fma2(accA[r], f1, wlo1); fma2(accB[r], f1, whi1);
            fma2(accA[r], f2, wlo2); fma2(accB[r], f2, whi2);
            fma2(accA[r], f3, wlo3); fma2(accB[r], f3, whi3);
        }
    }

    // ---- scale + LayerNorm + write ----
    float4 g4 = reinterpret_cast<const float4*>(gamma)[lane];
    float4 b4 = reinterpret_cast<const float4*>(beta)[lane];
    int Rbase = blockIdx.x * 64 + row0;

    #pragma unroll
    for (int r = 0; r < 8; r++) {
        float wt = g_weights[Rbase + r] + wB[r];
        float v0, v1, v2, v3;
        unpack2(accA[r], v0, v1);
        unpack2(accB[r], v2, v3);
        v0 *= wt; v1 *= wt; v2 *= wt; v3 *= wt;

        float t = v0 + v1 + v2 + v3;
        #pragma unroll
        for (int o = 16; o; o >>= 1) t += __shfl_xor_sync(0xffffffffu, t, o);
        float mu = t * (1.0f / Cc);
        float d0 = v0 - mu, d1 = v1 - mu, d2 = v2 - mu, d3 = v3 - mu;
        t = d0 * d0 + d1 * d1 + d2 * d2 + d3 * d3;
        #pragma unroll
        for (int o = 16; o; o >>= 1) t += __shfl_xor_sync(0xffffffffu, t, o);
        float rstd = rsqrtf(t * (1.0f / Cc) + LN_EPS);

        float4 o4 = make_float4(d0 * rstd * g4.x + b4.x,
                                d1 * rstd * g4.y + b4.y,
                                d2 * rstd * g4.z + b4.z,
                                d3 * rstd * g4.w + b4.w);
        reinterpret_cast<float4*>(out)[(size_t)(Rbase + r) * 32 + lane] = o4;
    }
}

// ---------------- launch ----------------------------------------------------
extern "C" void kernel_launch(void* const* d_in, const int* in_sizes, int n_in,
                              void* d_out, int out_size) {
    const float* x     = (const float*)d_in[0];
    const int*   erow  = (const int*)  d_in[1];
    const int*   ecol  = (const int*)  d_in[2];
    const float* evals = (const float*)d_in[3];
    const float* Wk    = (const float*)d_in[4];
    const float* Wq    = (const float*)d_in[5];
    const float* Wv    = (const float*)d_in[6];
    const float* gamma = (const float*)d_in[7];
    const float* beta  = (const float*)d_in[8];
    float* out = (float*)d_out;
    int E = in_sizes[1];
    if (E > Ec) E = Ec;

    setup_kernel<<<(Gc + 255) / 256, 256>>>(Wk, Wq);
    int eblk = ((E + 3) / 4 + 255) / 256;
    count_kernel<<<eblk, 256>>>(erow, E);
    scan_wx_kernel<<<1 + WT_BLOCKS, 1024>>>(x);            // scan || weights(x)
    scatter_kernel<<<eblk, 256>>>(erow, ecol, evals, E);

    spmm1_kernel<<<SPMM_BLOCKS, 256>>>(x);                 // x -> A
    spmm2_kernel<<<WT_BLOCKS + SPMM_BLOCKS, 256>>>();      // w(A) || A -> B

    static const int FINAL_SMEM = (Cc * Cc + 64 * Cc) * sizeof(float); // 96KB
    cudaFuncSetAttribute(final5_kernel,
                         cudaFuncAttributeMaxDynamicSharedMemorySize, FINAL_SMEM);
    final5_kernel<<<NROWS / 64, 256, FINAL_SMEM>>>(x, Wv, gamma, beta, out);
}

// round 9
// speedup vs baseline: 1.2810x; 1.0414x over previous
#include <cuda_runtime.h>
#include <cstdint>

// Problem constants (match reference)
#define Lc 4
#define Gc 20000
#define Cc 128
#define Ec 320000
#define KDc 16
#define NROWS (Lc*Gc)          // 80000 state rows of length 128
#define LN_EPS 1e-5f
#define CAP 192                // padded edge-bucket capacity per row

typedef unsigned long long u64;

#define WT_BLOCKS   (NROWS/32)   // 2500
#define SPMM_BLOCKS (Gc/2)       // 10000

// ---------------- device scratch (static: no allocation APIs) --------------
__device__ float g_bufA[(size_t)Lc*Gc*Cc];   // xr1
__device__ float g_bufB[(size_t)Lc*Gc*Cc];   // xr2
__device__ float g_weights[NROWS];           // flat index R = l*Gc + g
__device__ int   g_cnt[Gc];                  // row degree (built by scatter)
__device__ int2  g_edgeP[(size_t)Gc*CAP];    // (col, f32bits(val*0.5)) padded
// paired layout: g_Wkq2[(j2*32+d)*2 + {0,1}] = W(2*j2, d), W(2*j2+1, d)
__device__ float g_Wkq2[(Cc/2)*32*2];
// j-paired Wv: g_Wv2[(j2*Cc + c)*2 + {0,1}] = Wv[2*j2][c], Wv[2*j2+1][c]
__device__ float g_Wv2[Cc*Cc];

// ---------------- packed fp32x2 FMA helpers --------------------------------
__device__ __forceinline__ void fma2(u64& acc, u64 a, u64 b) {
    asm("fma.rn.f32x2 %0, %1, %2, %3;" : "=l"(acc) : "l"(a), "l"(b), "l"(acc));
}
__device__ __forceinline__ void unpack2(u64 v, float& lo, float& hi) {
    asm("mov.b64 {%0,%1}, %2;" : "=f"(lo), "=f"(hi) : "l"(v));
}
__device__ __forceinline__ float psum(u64 v) {
    float lo, hi;
    unpack2(v, lo, hi);
    return lo + hi;
}

// ---------------- setup: zero counters + paired Wkq2 + paired Wv2 ----------
__global__ void setup_kernel(const float* __restrict__ Wk,
                             const float* __restrict__ Wq,
                             const float* __restrict__ Wv) {
    int i = blockIdx.x * blockDim.x + threadIdx.x;
    if (i < Gc) g_cnt[i] = 0;
    if (i < (Cc / 2) * 32) {
        int j2 = i >> 5, d = i & 31;
        const float* W = (d < 16) ? Wk : Wq;
        int dd = d & 15;
        g_Wkq2[i * 2 + 0] = W[(2 * j2 + 0) * KDc + dd];
        g_Wkq2[i * 2 + 1] = W[(2 * j2 + 1) * KDc + dd];
    }
    if (i < Cc * Cc) {
        int j = i >> 7, c = i & 127;
        g_Wv2[((j >> 1) * Cc + c) * 2 + (j & 1)] = Wv[i];
    }
}

// ---------------- weights tile: 32 rows, 8 warps x 4 rows, lane = kq dim ----
__device__ __forceinline__ void weights_tile(const float* __restrict__ state,
                                             int b, int accum) {
    __shared__ __align__(16) float s[32][Cc];
    __shared__ __align__(16) float wkq2[(Cc/2)*32*2];
    int tid = threadIdx.x;                    // 256

    const float4* gp = reinterpret_cast<const float4*>(state + (size_t)b * 32 * Cc);
    float4* sp = reinterpret_cast<float4*>(&s[0][0]);
    const float4* wg = reinterpret_cast<const float4*>(g_Wkq2);
    float4* wsp = reinterpret_cast<float4*>(wkq2);
    #pragma unroll
    for (int i = 0; i < 4; i++) {
        sp[tid + i * 256]  = gp[tid + i * 256];
        wsp[tid + i * 256] = wg[tid + i * 256];
    }
    __syncthreads();

    int w = tid >> 5, lane = tid & 31;
    u64 acc[4] = {0ull, 0ull, 0ull, 0ull};
    #pragma unroll 8
    for (int j2 = 0; j2 < Cc / 2; j2++) {
        u64 w2 = *reinterpret_cast<const u64*>(wkq2 + (j2 * 32 + lane) * 2);
        #pragma unroll
        for (int r = 0; r < 4; r++) {
            u64 sv = *reinterpret_cast<const u64*>(&s[w * 4 + r][j2 * 2]);
            fma2(acc[r], sv, w2);
        }
    }
    #pragma unroll
    for (int r = 0; r < 4; r++) {
        float a = psum(acc[r]);
        float p = a * __shfl_xor_sync(0xffffffffu, a, 16);
        #pragma unroll
        for (int o = 8; o; o >>= 1)
            p += __shfl_xor_sync(0xffffffffu, p, o);
        if (lane == 0) {
            int R = b * 32 + w * 4 + r;
            float val = p * (1.0f / KDc);
            g_weights[R] = accum ? (g_weights[R] + val) : val;
        }
    }
}

// ---------------- scatter (padded buckets) + weights(x) ---------------------
__global__ void scatter_wx_kernel(const int* __restrict__ erow,
                                  const int* __restrict__ ecol,
                                  const float* __restrict__ ev,
                                  int E, int eblk,
                                  const float* __restrict__ x) {
    if ((int)blockIdx.x < eblk) {
        int i = (blockIdx.x * blockDim.x + threadIdx.x) * 4;
        if (i + 3 < E) {
            int4   r = *reinterpret_cast<const int4*>(erow + i);
            int4   c = *reinterpret_cast<const int4*>(ecol + i);
            float4 v = *reinterpret_cast<const float4*>(ev + i);
            int p;
            p = atomicAdd(&g_cnt[r.x], 1);
            g_edgeP[(size_t)r.x * CAP + p] = make_int2(c.x, __float_as_int(v.x * 0.5f));
            p = atomicAdd(&g_cnt[r.y], 1);
            g_edgeP[(size_t)r.y * CAP + p] = make_int2(c.y, __float_as_int(v.y * 0.5f));
            p = atomicAdd(&g_cnt[r.z], 1);
            g_edgeP[(size_t)r.z * CAP + p] = make_int2(c.z, __float_as_int(v.z * 0.5f));
            p = atomicAdd(&g_cnt[r.w], 1);
            g_edgeP[(size_t)r.w * CAP + p] = make_int2(c.w, __float_as_int(v.w * 0.5f));
        } else {
            for (int k = i; k < E; k++) {
                int p = atomicAdd(&g_cnt[erow[k]], 1);
                g_edgeP[(size_t)erow[k] * CAP + p] =
                    make_int2(ecol[k], __float_as_int(ev[k] * 0.5f));
            }
        }
    } else {
        weights_tile(x, blockIdx.x - eblk, 0);   // init g_weights
    }
}

// ---------------- spmm core: 4-edge batches, MLP>=4 -------------------------
__device__ __forceinline__ void spmm_warp(const float* __restrict__ src,
                                          float* __restrict__ dst,
                                          int g, int l, int lane) {
    int n = g_cnt[g];
    const int2* ep = g_edgeP + (size_t)g * CAP;
    const float* srcb = src + (size_t)l * Gc * Cc + lane * 4;
    float4 acc = make_float4(0.f, 0.f, 0.f, 0.f);
    int k = 0;
    for (; k + 4 <= n; k += 4) {
        int4 e01 = *reinterpret_cast<const int4*>(ep + k);       // broadcast
        int4 e23 = *reinterpret_cast<const int4*>(ep + k + 2);
        float4 s0 = *reinterpret_cast<const float4*>(srcb + (size_t)e01.x * Cc);
        float4 s1 = *reinterpret_cast<const float4*>(srcb + (size_t)e01.z * Cc);
        float4 s2 = *reinterpret_cast<const float4*>(srcb + (size_t)e23.x * Cc);
        float4 s3 = *reinterpret_cast<const float4*>(srcb + (size_t)e23.z * Cc);
        float v0 = __int_as_float(e01.y), v1 = __int_as_float(e01.w);
        float v2 = __int_as_float(e23.y), v3 = __int_as_float(e23.w);
        acc.x += v0 * s0.x + v1 * s1.x + v2 * s2.x + v3 * s3.x;
        acc.y += v0 * s0.y + v1 * s1.y + v2 * s2.y + v3 * s3.y;
        acc.z += v0 * s0.z + v1 * s1.z + v2 * s2.z + v3 * s3.z;
        acc.w += v0 * s0.w + v1 * s1.w + v2 * s2.w + v3 * s3.w;
    }
    for (; k < n; k++) {
        int2 cv = ep[k];
        float v = __int_as_float(cv.y);
        float4 sv = *reinterpret_cast<const float4*>(srcb + (size_t)cv.x * Cc);
        acc.x += v * sv.x; acc.y += v * sv.y;
        acc.z += v * sv.z; acc.w += v * sv.w;
    }
    *reinterpret_cast<float4*>(dst + ((size_t)l * Gc + g) * Cc + lane * 4) = acc;
}

// ---------------- spmm1: x -> A ---------------------------------------------
__global__ void spmm1_kernel(const float* __restrict__ x) {
    int w = threadIdx.x >> 5, lane = threadIdx.x & 31;
    int g = blockIdx.x * 2 + (w >> 2);
    spmm_warp(x, g_bufA, g, w & 3, lane);
}

// ---------------- spmm2 + weights(A): weights blocks first ------------------
__global__ void spmm2_kernel() {
    if (blockIdx.x >= WT_BLOCKS) {
        int b = blockIdx.x - WT_BLOCKS;
        int w = threadIdx.x >> 5, lane = threadIdx.x & 31;
        int g = b * 2 + (w >> 2);
        spmm_warp(g_bufA, g_bufB, g, w & 3, lane);
    } else {
        weights_tile(g_bufA, blockIdx.x, 1);    // accumulate
    }
}

// ---------------- final: wB + (x+A+B)@Wv * w + LayerNorm --------------------
// Block = 64 rows, 8 warps x 8 rows, lane = 4 output cols.
// GEMM uses j-paired operands: zero pack MOVs in the hot loop.
__global__ void __launch_bounds__(256, 2)
final6_kernel(const float* __restrict__ x,
              const float* __restrict__ gamma,
              const float* __restrict__ beta,
              float* __restrict__ out) {
    extern __shared__ __align__(16) float dyn[];
    float* wv2 = dyn;                                    // [64*128*2] 64KB paired
    float (*s)[Cc] = reinterpret_cast<float(*)[Cc]>(dyn + Cc * Cc);  // [64][128] 32KB

    int tid = threadIdx.x;              // 256
    size_t base = (size_t)blockIdx.x * 64 * Cc;

    // stage paired Wv (64KB) + B tile (32KB)
    const float4* wvg = reinterpret_cast<const float4*>(g_Wv2);
    float4* wvs = reinterpret_cast<float4*>(wv2);
    #pragma unroll
    for (int i = 0; i < 16; i++) wvs[tid + i * 256] = wvg[tid + i * 256];
    const float4* bp = reinterpret_cast<const float4*>(g_bufB + base);
    float4* sp = reinterpret_cast<float4*>(&s[0][0]);
    #pragma unroll
    for (int i = 0; i < 8; i++) sp[tid + i * 256] = bp[tid + i * 256];
    __syncthreads();

    int w = tid >> 5, lane = tid & 31;
    int row0 = w * 8;

    // ---- weight(B) contribution for this warp's 8 rows ----
    float wB[8];
    {
        u64 acc[8] = {0ull,0ull,0ull,0ull,0ull,0ull,0ull,0ull};
        #pragma unroll 4
        for (int j2 = 0; j2 < Cc / 2; j2++) {
            u64 w2 = *reinterpret_cast<const u64*>(g_Wkq2 + (j2 * 32 + lane) * 2);
            #pragma unroll
            for (int r = 0; r < 8; r++) {
                u64 sv = *reinterpret_cast<const u64*>(&s[row0 + r][j2 * 2]);
                fma2(acc[r], sv, w2);
            }
        }
        #pragma unroll
        for (int r = 0; r < 8; r++) {
            float a = psum(acc[r]);
            float p = a * __shfl_xor_sync(0xffffffffu, a, 16);
            #pragma unroll
            for (int o = 8; o; o >>= 1)
                p += __shfl_xor_sync(0xffffffffu, p, o);
            wB[r] = p * (1.0f / KDc);
        }
    }
    __syncthreads();                    // everyone done reading B tile

    // ---- s = B + x + A ----
    const float4* xp = reinterpret_cast<const float4*>(x + base);
    const float4* ap = reinterpret_cast<const float4*>(g_bufA + base);
    #pragma unroll
    for (int i = 0; i < 8; i++) {
        float4 a = xp[tid + i * 256];
        float4 b = ap[tid + i * 256];
        float4 c = sp[tid + i * 256];
        sp[tid + i * 256] = make_float4(a.x + b.x + c.x, a.y + b.y + c.y,
                                        a.z + b.z + c.z, a.w + b.w + c.w);
    }
    __syncthreads();

    // ---- GEMM: j-paired. acc[r][c] = (even-j partial, odd-j partial) ----
    u64 acc[8][4];
    #pragma unroll
    for (int r = 0; r < 8; r++)
        #pragma unroll
        for (int c = 0; c < 4; c++) acc[r][c] = 0ull;

    #pragma unroll 2
    for (int j2 = 0; j2 < Cc / 2; j2++) {
        const u64* wp = reinterpret_cast<const u64*>(wv2) + j2 * Cc + lane * 4;
        u64 w0 = wp[0], w1 = wp[1], w2 = wp[2], w3 = wp[3];
        #pragma unroll
        for (int r = 0; r < 8; r++) {
            u64 sv = *reinterpret_cast<const u64*>(&s[row0 + r][j2 * 2]);  // broadcast
            fma2(acc[r][0], sv, w0);
            fma2(acc[r][1], sv, w1);
            fma2(acc[r][2], sv, w2);
            fma2(acc[r][3], sv, w3);
        }
    }

    // ---- scale + LayerNorm + write ----
    float4 g4 = reinterpret_cast<const float4*>(gamma)[lane];
    float4 b4 = reinterpret_cast<const float4*>(beta)[lane];
    int Rbase = blockIdx.x * 64 + row0;

    #pragma unroll
    for (int r = 0; r < 8; r++) {
        float wt = g_weights[Rbase + r] + wB[r];
        float v0 = psum(acc[r][0]) * wt;
        float v1 = psum(acc[r][1]) * wt;
        float v2 = psum(acc[r][2]) * wt;
        float v3 = psum(acc[r][3]) * wt;

        float t = v0 + v1 + v2 + v3;
        #pragma unroll
        for (int o = 16; o; o >>= 1) t += __shfl_xor_sync(0xffffffffu, t, o);
        float mu = t * (1.0f / Cc);
        float d0 = v0 - mu, d1 = v1 - mu, d2 = v2 - mu, d3 = v3 - mu;
        t = d0 * d0 + d1 * d1 + d2 * d2 + d3 * d3;
        #pragma unroll
        for (int o = 16; o; o >>= 1) t += __shfl_xor_sync(0xffffffffu, t, o);
        float rstd = rsqrtf(t * (1.0f / Cc) + LN_EPS);

        float4 o4 = make_float4(d0 * rstd * g4.x + b4.x,
                                d1 * rstd * g4.y + b4.y,
                                d2 * rstd * g4.z + b4.z,
                                d3 * rstd * g4.w + b4.w);
        reinterpret_cast<float4*>(out)[(size_t)(Rbase + r) * 32 + lane] = o4;
    }
}

// ---------------- launch ----------------------------------------------------
extern "C" void kernel_launch(void* const* d_in, const int* in_sizes, int n_in,
                              void* d_out, int out_size) {
    const float* x     = (const float*)d_in[0];
    const int*   erow  = (const int*)  d_in[1];
    const int*   ecol  = (const int*)  d_in[2];
    const float* evals = (const float*)d_in[3];
    const float* Wk    = (const float*)d_in[4];
    const float* Wq    = (const float*)d_in[5];
    const float* Wv    = (const float*)d_in[6];
    const float* gamma = (const float*)d_in[7];
    const float* beta  = (const float*)d_in[8];
    float* out = (float*)d_out;
    int E = in_sizes[1];
    if (E > Ec) E = Ec;

    setup_kernel<<<(Gc + 255) / 256, 256>>>(Wk, Wq, Wv);

    int eblk = ((E + 3) / 4 + 255) / 256;                      // 313
    scatter_wx_kernel<<<eblk + WT_BLOCKS, 256>>>(erow, ecol, evals, E, eblk, x);

    spmm1_kernel<<<SPMM_BLOCKS, 256>>>(x);                     // x -> A
    spmm2_kernel<<<WT_BLOCKS + SPMM_BLOCKS, 256>>>();          // w(A) || A -> B

    static const int FINAL_SMEM = (Cc * Cc + 64 * Cc) * sizeof(float); // 96KB
    cudaFuncSetAttribute(final6_kernel,
                         cudaFuncAttributeMaxDynamicSharedMemorySize, FINAL_SMEM);
    final6_kernel<<<NROWS / 64, 256, FINAL_SMEM>>>(x, gamma, beta, out);
}